// round 8
// baseline (speedup 1.0000x reference)
#include <cuda_runtime.h>
#include <cuda_fp16.h>
#include <math.h>
#include <stdint.h>

// ---------------- problem constants ----------------
#define B_SZ   128
#define K_SZ   256
#define M_SZ   8
#define D_SZ   128
#define NQ     (B_SZ * K_SZ)   // 32768 query rows
#define NP     (K_SZ * M_SZ)   // 2048 prototype rows

#define GAMMA_F  20.0f
#define LAMBDA_F 20.0f
#define MARGIN_F 0.05f
#define EPS_F    1e-8f

// ---------------- tile config ----------------
#define BM 128              // query rows per CTA
#define BN 128              // prototype rows per chunk (16 concepts)
#define NCHUNK (NP / BN)    // 16
#define NTHREADS 512        // 16 warps: warp_m = w>>2 (4, 32 rows), warp_n = w&3 (4, 32 cols)
#define NCTAS (NQ / BM)     // 256

// padded fp16 tile row stride: 128 halves = 256B + 16B pad (conflict-free ldmatrix)
#define TSTRIDE 272

#define OFF_A   0
#define OFF_B0  (BM * TSTRIDE)            // 34816
#define OFF_B1  (OFF_B0 + BN * TSTRIDE)   // 69632
#define OFF_RED (OFF_B1 + BN * TSTRIDE)   // 104448
#define SMEM_BYTES (OFF_RED + 2 * BM * 4) // 105472

__device__ float g_loss_sum;   // zero-init at load; reset by last CTA each call
__device__ int   g_pos_cnt;
__device__ unsigned int g_done;

// fp16 copies, written by cvt kernel each call (deterministic overwrite)
__device__ __half V16[NQ * D_SZ];
__device__ __half P16[NP * D_SZ];

__device__ __forceinline__ uint32_t smem_u32(const void* p) {
    uint32_t a;
    asm("{ .reg .u64 t; cvta.to.shared.u64 t, %1; cvt.u32.u64 %0, t; }" : "=r"(a) : "l"(p));
    return a;
}

__device__ __forceinline__ void ldsm_x4(uint32_t& r0, uint32_t& r1, uint32_t& r2, uint32_t& r3,
                                        uint32_t addr) {
    asm volatile("ldmatrix.sync.aligned.m8n8.x4.shared.b16 {%0,%1,%2,%3}, [%4];"
                 : "=r"(r0), "=r"(r1), "=r"(r2), "=r"(r3) : "r"(addr));
}

__device__ __forceinline__ void mma_f16(float* c, uint32_t a0, uint32_t a1, uint32_t a2,
                                        uint32_t a3, uint32_t b0, uint32_t b1) {
    asm volatile(
        "mma.sync.aligned.m16n8k16.row.col.f32.f16.f16.f32 "
        "{%0,%1,%2,%3}, {%4,%5,%6,%7}, {%8,%9}, {%0,%1,%2,%3};"
        : "+f"(c[0]), "+f"(c[1]), "+f"(c[2]), "+f"(c[3])
        : "r"(a0), "r"(a1), "r"(a2), "r"(a3), "r"(b0), "r"(b1));
}

__device__ __forceinline__ void cp_async16(uint32_t saddr, const void* gptr) {
    asm volatile("cp.async.cg.shared.global [%0], [%1], 16;" :: "r"(saddr), "l"(gptr));
}
#define CP_COMMIT() asm volatile("cp.async.commit_group;" ::: "memory")
#define CP_WAIT0()  asm volatile("cp.async.wait_group 0;" ::: "memory")

__device__ __forceinline__ uint32_t pack2h(float a, float b) {
    __half2 t = __floats2half2_rn(a, b);
    return *reinterpret_cast<uint32_t*>(&t);
}

// cp.async a 128-row x 128-col fp16 tile (row-major src) into padded smem layout
__device__ __forceinline__ void issue_tile(uint32_t dst_sb, const __half* __restrict__ src,
                                           int tid) {
    #pragma unroll
    for (int i = 0; i < 4; i++) {
        int linear = tid + i * NTHREADS;   // 16B line index (2048 total)
        int row  = linear >> 4;
        int line = linear & 15;
        cp_async16(dst_sb + (uint32_t)row * TSTRIDE + (uint32_t)line * 16,
                   src + (size_t)row * D_SZ + line * 8);
    }
    CP_COMMIT();
}

// ---- fp32 -> fp16 precompute (V then P, flat float4 indexing) ----
__global__ void mpc_cvt_kernel(const float* __restrict__ V, const float* __restrict__ P) {
    int i = blockIdx.x * blockDim.x + threadIdx.x;
    const int nv4 = NQ * D_SZ / 4;
    const int np4 = NP * D_SZ / 4;
    if (i < nv4) {
        float4 v = __ldg(reinterpret_cast<const float4*>(V) + i);
        *reinterpret_cast<uint2*>(&V16[i * 4]) =
            make_uint2(pack2h(v.x, v.y), pack2h(v.z, v.w));
    } else if (i < nv4 + np4) {
        int j = i - nv4;
        float4 v = __ldg(reinterpret_cast<const float4*>(P) + j);
        *reinterpret_cast<uint2*>(&P16[j * 4]) =
            make_uint2(pack2h(v.x, v.y), pack2h(v.z, v.w));
    }
}

__global__ __launch_bounds__(NTHREADS, 2)
void mpc_main_kernel(const int* __restrict__ labels, float* __restrict__ out)
{
    extern __shared__ char smem[];
    const uint32_t sb = smem_u32(smem);
    const int tid  = threadIdx.x;
    const int warp = tid >> 5;
    const int lane = tid & 31;
    const int warp_m = warp >> 2;   // 0..3 -> rows 32*warp_m
    const int warp_n = warp & 3;    // 0..3 -> cols 32*warp_n
    const int rowBase = blockIdx.x * BM;
    const int kbase   = rowBase & (K_SZ - 1);   // 0 or 128

    float* denom_s = reinterpret_cast<float*>(smem + OFF_RED);
    float* sims_s  = denom_s + BM;
    if (tid < BM) { denom_s[tid] = 0.0f; sims_s[tid] = 0.0f; }

    // ---- prologue: A tile + B chunk 0 straight into MMA layout ----
    issue_tile(sb + OFF_A, V16 + (size_t)rowBase * D_SZ, tid);
    issue_tile(sb + OFF_B0, P16, tid);
    CP_WAIT0();
    __syncthreads();

    // lane-invariant ldmatrix address components
    const uint32_t aLane = (uint32_t)(warp_m * 32 + (lane & 15)) * TSTRIDE
                         + (uint32_t)(lane >> 4) * 16;
    const uint32_t bLane = (uint32_t)(warp_n * 32 + ((lane >> 4) << 3) + (lane & 7)) * TSTRIDE
                         + (uint32_t)((lane >> 3) & 1) * 16;
    const uint32_t aB0 = sb + OFF_A + aLane;
    const uint32_t aB1 = aB0 + 16u * TSTRIDE;

    float denomAcc[4], simPos[4];   // [2*mf + lowhigh]
    #pragma unroll
    for (int i = 0; i < 4; i++) { denomAcc[i] = 0.0f; simPos[i] = 0.0f; }

    #pragma unroll 1
    for (int chunk = 0; chunk < NCHUNK; ++chunk) {
        // prefetch next chunk's B directly into the other buffer.
        // Safe: that buffer was last read during chunk-1's MMA, which every warp
        // finished before the barrier at the end of chunk-1.
        if (chunk + 1 < NCHUNK)
            issue_tile(sb + (((chunk + 1) & 1) ? OFF_B1 : OFF_B0),
                       P16 + (size_t)((chunk + 1) * BN) * D_SZ, tid);

        const uint32_t bB0 = sb + ((chunk & 1) ? OFF_B1 : OFF_B0) + bLane;
        const uint32_t bB1 = bB0 + 16u * TSTRIDE;

        float acc[2][4][4];
        #pragma unroll
        for (int mf = 0; mf < 2; mf++)
            #pragma unroll
            for (int nf = 0; nf < 4; nf++)
                #pragma unroll
                for (int q = 0; q < 4; q++)
                    acc[mf][nf][q] = 0.0f;

        // single-pass fp16: per k-step 4 LDSM feed 8 MMAs
        #pragma unroll
        for (int ks = 0; ks < 8; ++ks) {
            const uint32_t ko = (uint32_t)ks * 32;
            uint32_t a0[4], a1[4];
            ldsm_x4(a0[0], a0[1], a0[2], a0[3], aB0 + ko);
            ldsm_x4(a1[0], a1[1], a1[2], a1[3], aB1 + ko);
            uint32_t b0, b1, b2, b3, b4, b5, b6, b7;
            ldsm_x4(b0, b1, b2, b3, bB0 + ko);   // cols 0-15: (b0,b1)=nf0, (b2,b3)=nf1
            ldsm_x4(b4, b5, b6, b7, bB1 + ko);   // cols 16-31: nf2, nf3

            mma_f16(acc[0][0], a0[0], a0[1], a0[2], a0[3], b0, b1);
            mma_f16(acc[0][1], a0[0], a0[1], a0[2], a0[3], b2, b3);
            mma_f16(acc[0][2], a0[0], a0[1], a0[2], a0[3], b4, b5);
            mma_f16(acc[0][3], a0[0], a0[1], a0[2], a0[3], b6, b7);
            mma_f16(acc[1][0], a1[0], a1[1], a1[2], a1[3], b0, b1);
            mma_f16(acc[1][1], a1[0], a1[1], a1[2], a1[3], b2, b3);
            mma_f16(acc[1][2], a1[0], a1[1], a1[2], a1[3], b4, b5);
            mma_f16(acc[1][3], a1[0], a1[1], a1[2], a1[3], b6, b7);
        }

        // wait own cp.asyncs, then barrier (all warps' copies visible + all done
        // reading buf[chunk&1]); epilogue after the barrier so it overlaps other
        // warps' MMA(chunk+1) without an intervening barrier.
        if (chunk + 1 < NCHUNK) CP_WAIT0();
        __syncthreads();

        // ---- fused epilogue: quad spans one concept's 8 prototypes ----
        #pragma unroll
        for (int mf = 0; mf < 2; ++mf) {
            const int rl = warp_m * 32 + mf * 16 + (lane >> 2);   // low row (high = rl+8)
            #pragma unroll
            for (int nf = 0; nf < 4; ++nf) {
                float c0 = acc[mf][nf][0], c1 = acc[mf][nf][1];
                float c2 = acc[mf][nf][2], c3 = acc[mf][nf][3];
                float e0 = __expf(GAMMA_F * c0), e1 = __expf(GAMMA_F * c1);
                float e2 = __expf(GAMMA_F * c2), e3 = __expf(GAMMA_F * c3);
                float Zl = e0 + e1, Wl = fmaf(e0, c0, e1 * c1);
                float Zh = e2 + e3, Wh = fmaf(e2, c2, e3 * c3);
                #pragma unroll
                for (int o = 1; o <= 2; o <<= 1) {
                    Zl += __shfl_xor_sync(0xffffffffu, Zl, o);
                    Wl += __shfl_xor_sync(0xffffffffu, Wl, o);
                    Zh += __shfl_xor_sync(0xffffffffu, Zh, o);
                    Wh += __shfl_xor_sync(0xffffffffu, Wh, o);
                }
                if ((lane & 3) == 0) {
                    float sl = __fdividef(Wl, Zl);
                    float sh = __fdividef(Wh, Zh);
                    denomAcc[2 * mf]     += __expf(LAMBDA_F * sl);
                    denomAcc[2 * mf + 1] += __expf(LAMBDA_F * sh);
                    int cg = chunk * 16 + warp_n * 4 + nf;       // global concept
                    if (cg == kbase + rl)     simPos[2 * mf]     = sl;
                    if (cg == kbase + rl + 8) simPos[2 * mf + 1] = sh;
                }
            }
        }
    }

    // ---- per-row combine across warp_n via smem atomics ----
    __syncthreads();
    if ((lane & 3) == 0) {
        #pragma unroll
        for (int mf = 0; mf < 2; ++mf) {
            int r = warp_m * 32 + mf * 16 + (lane >> 2);
            atomicAdd(&denom_s[r],     denomAcc[2 * mf]);
            atomicAdd(&denom_s[r + 8], denomAcc[2 * mf + 1]);
            atomicAdd(&sims_s[r],      simPos[2 * mf]);
            atomicAdd(&sims_s[r + 8],  simPos[2 * mf + 1]);
        }
    }
    __syncthreads();

    float lsum = 0.0f;
    int   lcnt = 0;
    if (tid < BM) {
        float d = denom_s[tid];
        float p = sims_s[tid];
        float loss = __logf(d + EPS_F) - LAMBDA_F * (p + MARGIN_F);
        if (labels[rowBase + tid] == 1) { lsum = loss; lcnt = 1; }
    }
    #pragma unroll
    for (int o = 16; o > 0; o >>= 1) {
        lsum += __shfl_xor_sync(0xffffffffu, lsum, o);
        lcnt += __shfl_xor_sync(0xffffffffu, lcnt, o);
    }
    __shared__ float ws[16];
    __shared__ int   wc[16];
    if (lane == 0) { ws[warp] = lsum; wc[warp] = lcnt; }
    __syncthreads();

    // ---- single-launch finalize: last CTA writes out, resets globals ----
    if (tid == 0) {
        float s = 0.0f; int n = 0;
        #pragma unroll
        for (int i = 0; i < 16; i++) { s += ws[i]; n += wc[i]; }
        atomicAdd(&g_loss_sum, s);
        atomicAdd(&g_pos_cnt, n);
        __threadfence();
        unsigned int old = atomicAdd(&g_done, 1u);
        if (old == NCTAS - 1) {
            float ts = g_loss_sum;
            int   tn = g_pos_cnt;
            out[0] = (tn > 0) ? (ts / (float)tn) : ts;
            g_loss_sum = 0.0f;
            g_pos_cnt  = 0;
            __threadfence();
            g_done = 0u;
        }
    }
}

extern "C" void kernel_launch(void* const* d_in, const int* in_sizes, int n_in,
                              void* d_out, int out_size)
{
    const float* V = nullptr;
    const int*   L = nullptr;
    const float* P = nullptr;
    for (int i = 0; i < n_in; i++) {
        if      (in_sizes[i] == NQ * D_SZ) V = (const float*)d_in[i];
        else if (in_sizes[i] == NQ)        L = (const int*)d_in[i];
        else if (in_sizes[i] == NP * D_SZ) P = (const float*)d_in[i];
    }

    cudaFuncSetAttribute(mpc_main_kernel,
                         cudaFuncAttributeMaxDynamicSharedMemorySize, SMEM_BYTES);

    const int total4 = (NQ + NP) * D_SZ / 4;
    mpc_cvt_kernel<<<(total4 + 255) / 256, 256>>>(V, P);
    mpc_main_kernel<<<NCTAS, NTHREADS, SMEM_BYTES>>>(L, (float*)d_out);
}

// round 9
// speedup vs baseline: 1.3171x; 1.3171x over previous
#include <cuda_runtime.h>
#include <cuda_fp16.h>
#include <math.h>
#include <stdint.h>

// ---------------- problem constants ----------------
#define B_SZ   128
#define K_SZ   256
#define M_SZ   8
#define D_SZ   128
#define NQ     (B_SZ * K_SZ)   // 32768 query rows
#define NP     (K_SZ * M_SZ)   // 2048 prototype rows

#define GAMMA_F  20.0f
#define LAMBDA_F 20.0f
#define MARGIN_F 0.05f
#define EPS_F    1e-8f

// ---------------- tile config ----------------
#define BM 128              // query rows per CTA
#define BN 128              // prototype rows per chunk (16 concepts)
#define NCHUNK (NP / BN)    // 16
#define NTHREADS 512        // 16 warps: warp_m = w>>2 (4, 32 rows), warp_n = w&3 (4, 32 cols)
#define NCTAS (NQ / BM)     // 256

// padded fp16 tile row stride: 128 halves = 256B + 16B pad (conflict-free ldmatrix)
#define TSTRIDE 272

#define OFF_A   0
#define OFF_B0  (BM * TSTRIDE)            // 34816
#define OFF_B1  (OFF_B0 + BN * TSTRIDE)   // 69632
#define OFF_RED (OFF_B1 + BN * TSTRIDE)   // 104448
#define SMEM_BYTES (OFF_RED + 2 * BM * 4) // 105472

__device__ float g_loss_sum;   // zero-init at load; reset by last CTA each call
__device__ int   g_pos_cnt;
__device__ unsigned int g_done;

// fp16 PERMUTED prototypes, written by cvt kernel each call.
// Within each 128-row chunk, proto (c_local, m) is stored at row
//   (c_local>>2)*32 + (m>>1)*8 + (c_local&3)*2 + (m&1)
// so that after MMA, thread t=lane&3 of each quad owns the full 8-proto group
// of concept warp_n*4 + t in its accumulator registers (no shuffles needed).
__device__ __half P16[NP * D_SZ];

__device__ __forceinline__ uint32_t smem_u32(const void* p) {
    uint32_t a;
    asm("{ .reg .u64 t; cvta.to.shared.u64 t, %1; cvt.u32.u64 %0, t; }" : "=r"(a) : "l"(p));
    return a;
}

__device__ __forceinline__ void ldsm_x4(uint32_t& r0, uint32_t& r1, uint32_t& r2, uint32_t& r3,
                                        uint32_t addr) {
    asm volatile("ldmatrix.sync.aligned.m8n8.x4.shared.b16 {%0,%1,%2,%3}, [%4];"
                 : "=r"(r0), "=r"(r1), "=r"(r2), "=r"(r3) : "r"(addr));
}

__device__ __forceinline__ void mma_f16(float* c, uint32_t a0, uint32_t a1, uint32_t a2,
                                        uint32_t a3, uint32_t b0, uint32_t b1) {
    asm volatile(
        "mma.sync.aligned.m16n8k16.row.col.f32.f16.f16.f32 "
        "{%0,%1,%2,%3}, {%4,%5,%6,%7}, {%8,%9}, {%0,%1,%2,%3};"
        : "+f"(c[0]), "+f"(c[1]), "+f"(c[2]), "+f"(c[3])
        : "r"(a0), "r"(a1), "r"(a2), "r"(a3), "r"(b0), "r"(b1));
}

__device__ __forceinline__ void cp_async16(uint32_t saddr, const void* gptr) {
    asm volatile("cp.async.cg.shared.global [%0], [%1], 16;" :: "r"(saddr), "l"(gptr));
}
#define CP_COMMIT() asm volatile("cp.async.commit_group;" ::: "memory")
#define CP_WAIT0()  asm volatile("cp.async.wait_group 0;" ::: "memory")

__device__ __forceinline__ uint32_t pack2h(float a, float b) {
    __half2 t = __floats2half2_rn(a, b);
    return *reinterpret_cast<uint32_t*>(&t);
}

// cp.async a 128-row x 128-col fp16 tile (row-major src) into padded smem layout
__device__ __forceinline__ void issue_tile(uint32_t dst_sb, const __half* __restrict__ src,
                                           int tid) {
    #pragma unroll
    for (int i = 0; i < 4; i++) {
        int linear = tid + i * NTHREADS;   // 16B line index (2048 total)
        int row  = linear >> 4;
        int line = linear & 15;
        cp_async16(dst_sb + (uint32_t)row * TSTRIDE + (uint32_t)line * 16,
                   src + (size_t)row * D_SZ + line * 8);
    }
    CP_COMMIT();
}

// ---- P fp32 -> fp16 with concept-ownership permutation ----
__global__ void mpc_cvt_kernel(const float* __restrict__ P) {
    int i = blockIdx.x * blockDim.x + threadIdx.x;   // float4 index
    if (i < NP * D_SZ / 4) {
        int row  = i >> 5;           // global proto row
        int col4 = i & 31;
        int chunk = row >> 7;
        int p     = row & 127;
        int c_loc = p >> 3, m = p & 7;
        int r2 = ((c_loc >> 2) << 5) + ((m >> 1) << 3) + ((c_loc & 3) << 1) + (m & 1);
        float4 v = __ldg(reinterpret_cast<const float4*>(P) + i);
        *reinterpret_cast<uint2*>(&P16[((size_t)((chunk << 7) + r2)) * D_SZ + col4 * 4]) =
            make_uint2(pack2h(v.x, v.y), pack2h(v.z, v.w));
    }
}

__global__ __launch_bounds__(NTHREADS, 2)
void mpc_main_kernel(const float* __restrict__ V,
                     const int*   __restrict__ labels,
                     float* __restrict__ out)
{
    extern __shared__ char smem[];
    const uint32_t sb = smem_u32(smem);
    const int tid  = threadIdx.x;
    const int warp = tid >> 5;
    const int lane = tid & 31;
    const int warp_m = warp >> 2;   // 0..3 -> rows 32*warp_m
    const int warp_n = warp & 3;    // 0..3 -> cols 32*warp_n
    const int rowBase = blockIdx.x * BM;
    const int kbase   = rowBase & (K_SZ - 1);   // 0 or 128

    float* denom_s = reinterpret_cast<float*>(smem + OFF_RED);
    float* sims_s  = denom_s + BM;
    if (tid < BM) { denom_s[tid] = 0.0f; sims_s[tid] = 0.0f; }

    // ---- B chunk 0 (fp16, permuted) via cp.async; A converted inline ----
    issue_tile(sb + OFF_B0, P16, tid);
    {
        const float4* gv = reinterpret_cast<const float4*>(V + (size_t)rowBase * D_SZ);
        #pragma unroll
        for (int i = 0; i < 8; i++) {
            int linear = tid + i * NTHREADS;   // float4 index (4096 total)
            int row  = linear >> 5;
            int col4 = linear & 31;
            float4 v = __ldg(gv + linear);
            *reinterpret_cast<uint2*>(smem + OFF_A + (uint32_t)row * TSTRIDE
                                      + (uint32_t)col4 * 8) =
                make_uint2(pack2h(v.x, v.y), pack2h(v.z, v.w));
        }
    }
    CP_WAIT0();
    __syncthreads();

    // lane-invariant ldmatrix address components
    const uint32_t aLane = (uint32_t)(warp_m * 32 + (lane & 15)) * TSTRIDE
                         + (uint32_t)(lane >> 4) * 16;
    const uint32_t bLane = (uint32_t)(warp_n * 32 + ((lane >> 4) << 3) + (lane & 7)) * TSTRIDE
                         + (uint32_t)((lane >> 3) & 1) * 16;
    const uint32_t aB0 = sb + OFF_A + aLane;
    const uint32_t aB1 = aB0 + 16u * TSTRIDE;

    // this thread's concept-within-chunk and rows
    const int ct    = warp_n * 4 + (lane & 3);
    const int rlow  = warp_m * 32 + (lane >> 2);   // + mf*16 + hr*8

    float denomAcc[4], simPos[4];   // [2*mf + hr]
    #pragma unroll
    for (int i = 0; i < 4; i++) { denomAcc[i] = 0.0f; simPos[i] = 0.0f; }

    #pragma unroll 1
    for (int chunk = 0; chunk < NCHUNK; ++chunk) {
        // prefetch next chunk's B into the other buffer (safe: last read pre-barrier)
        if (chunk + 1 < NCHUNK)
            issue_tile(sb + (((chunk + 1) & 1) ? OFF_B1 : OFF_B0),
                       P16 + (size_t)((chunk + 1) * BN) * D_SZ, tid);

        const uint32_t bB0 = sb + ((chunk & 1) ? OFF_B1 : OFF_B0) + bLane;
        const uint32_t bB1 = bB0 + 16u * TSTRIDE;

        float acc[2][4][4];
        #pragma unroll
        for (int mf = 0; mf < 2; mf++)
            #pragma unroll
            for (int nf = 0; nf < 4; nf++)
                #pragma unroll
                for (int q = 0; q < 4; q++)
                    acc[mf][nf][q] = 0.0f;

        // single-pass fp16: per k-step 4 LDSM feed 8 MMAs
        #pragma unroll
        for (int ks = 0; ks < 8; ++ks) {
            const uint32_t ko = (uint32_t)ks * 32;
            uint32_t a0[4], a1[4];
            ldsm_x4(a0[0], a0[1], a0[2], a0[3], aB0 + ko);
            ldsm_x4(a1[0], a1[1], a1[2], a1[3], aB1 + ko);
            uint32_t b0, b1, b2, b3, b4, b5, b6, b7;
            ldsm_x4(b0, b1, b2, b3, bB0 + ko);   // rows 0-15 of slice: nf0, nf1
            ldsm_x4(b4, b5, b6, b7, bB1 + ko);   // rows 16-31: nf2, nf3

            mma_f16(acc[0][0], a0[0], a0[1], a0[2], a0[3], b0, b1);
            mma_f16(acc[0][1], a0[0], a0[1], a0[2], a0[3], b2, b3);
            mma_f16(acc[0][2], a0[0], a0[1], a0[2], a0[3], b4, b5);
            mma_f16(acc[0][3], a0[0], a0[1], a0[2], a0[3], b6, b7);
            mma_f16(acc[1][0], a1[0], a1[1], a1[2], a1[3], b0, b1);
            mma_f16(acc[1][1], a1[0], a1[1], a1[2], a1[3], b2, b3);
            mma_f16(acc[1][2], a1[0], a1[1], a1[2], a1[3], b4, b5);
            mma_f16(acc[1][3], a1[0], a1[1], a1[2], a1[3], b6, b7);
        }

        if (chunk + 1 < NCHUNK) CP_WAIT0();
        __syncthreads();

        // ---- register-local epilogue: thread owns concept ct's full 8-proto
        // group for rows rlow + mf*16 + hr*8 (permuted B). No shuffles. ----
        const int cg = chunk * 16 + ct;   // global concept this thread owns
        #pragma unroll
        for (int mf = 0; mf < 2; ++mf) {
            #pragma unroll
            for (int hr = 0; hr < 2; ++hr) {
                // proto m value = acc[mf][m>>1][hr*2 + (m&1)]
                float Z = 0.0f, W = 0.0f;
                #pragma unroll
                for (int nf = 0; nf < 4; ++nf) {
                    float sa = acc[mf][nf][hr * 2];
                    float sc = acc[mf][nf][hr * 2 + 1];
                    float ea = __expf(GAMMA_F * sa);
                    float ec = __expf(GAMMA_F * sc);
                    Z += ea + ec;
                    W = fmaf(ea, sa, W);
                    W = fmaf(ec, sc, W);
                }
                float sim = __fdividef(W, Z);
                denomAcc[2 * mf + hr] += __expf(LAMBDA_F * sim);
                int row = rlow + mf * 16 + hr * 8;
                if (cg == kbase + row) simPos[2 * mf + hr] = sim;
            }
        }
    }

    // ---- quad reduce (4 concepts -> per-row partials), then smem atomics ----
    #pragma unroll
    for (int o = 1; o <= 2; o <<= 1) {
        #pragma unroll
        for (int i = 0; i < 4; i++) {
            denomAcc[i] += __shfl_xor_sync(0xffffffffu, denomAcc[i], o);
            simPos[i]   += __shfl_xor_sync(0xffffffffu, simPos[i], o);
        }
    }
    __syncthreads();
    if ((lane & 3) == 0) {
        #pragma unroll
        for (int mf = 0; mf < 2; ++mf) {
            int r = rlow + mf * 16;
            atomicAdd(&denom_s[r],     denomAcc[2 * mf]);
            atomicAdd(&denom_s[r + 8], denomAcc[2 * mf + 1]);
            atomicAdd(&sims_s[r],      simPos[2 * mf]);
            atomicAdd(&sims_s[r + 8],  simPos[2 * mf + 1]);
        }
    }
    __syncthreads();

    float lsum = 0.0f;
    int   lcnt = 0;
    if (tid < BM) {
        float d = denom_s[tid];
        float p = sims_s[tid];
        float loss = __logf(d + EPS_F) - LAMBDA_F * (p + MARGIN_F);
        if (labels[rowBase + tid] == 1) { lsum = loss; lcnt = 1; }
    }
    #pragma unroll
    for (int o = 16; o > 0; o >>= 1) {
        lsum += __shfl_xor_sync(0xffffffffu, lsum, o);
        lcnt += __shfl_xor_sync(0xffffffffu, lcnt, o);
    }
    __shared__ float ws[16];
    __shared__ int   wc[16];
    if (lane == 0) { ws[warp] = lsum; wc[warp] = lcnt; }
    __syncthreads();

    // ---- single-launch finalize: last CTA writes out, resets globals ----
    if (tid == 0) {
        float s = 0.0f; int n = 0;
        #pragma unroll
        for (int i = 0; i < 16; i++) { s += ws[i]; n += wc[i]; }
        atomicAdd(&g_loss_sum, s);
        atomicAdd(&g_pos_cnt, n);
        __threadfence();
        unsigned int old = atomicAdd(&g_done, 1u);
        if (old == NCTAS - 1) {
            float ts = g_loss_sum;
            int   tn = g_pos_cnt;
            out[0] = (tn > 0) ? (ts / (float)tn) : ts;
            g_loss_sum = 0.0f;
            g_pos_cnt  = 0;
            __threadfence();
            g_done = 0u;
        }
    }
}

extern "C" void kernel_launch(void* const* d_in, const int* in_sizes, int n_in,
                              void* d_out, int out_size)
{
    const float* V = nullptr;
    const int*   L = nullptr;
    const float* P = nullptr;
    for (int i = 0; i < n_in; i++) {
        if      (in_sizes[i] == NQ * D_SZ) V = (const float*)d_in[i];
        else if (in_sizes[i] == NQ)        L = (const int*)d_in[i];
        else if (in_sizes[i] == NP * D_SZ) P = (const float*)d_in[i];
    }

    cudaFuncSetAttribute(mpc_main_kernel,
                         cudaFuncAttributeMaxDynamicSharedMemorySize, SMEM_BYTES);

    const int np4 = NP * D_SZ / 4;   // 65536 float4
    mpc_cvt_kernel<<<(np4 + 255) / 256, 256>>>(P);
    mpc_main_kernel<<<NCTAS, NTHREADS, SMEM_BYTES>>>(V, L, (float*)d_out);
}

// round 10
// speedup vs baseline: 1.3176x; 1.0004x over previous
#include <cuda_runtime.h>
#include <cuda_fp16.h>
#include <math.h>
#include <stdint.h>

// ---------------- problem constants ----------------
#define B_SZ   128
#define K_SZ   256
#define M_SZ   8
#define D_SZ   128
#define NQ     (B_SZ * K_SZ)   // 32768 query rows
#define NP     (K_SZ * M_SZ)   // 2048 prototype rows

#define GAMMA_F  20.0f
#define LAMBDA_F 20.0f
#define MARGIN_F 0.05f
#define EPS_F    1e-8f

// ---------------- tile config ----------------
#define BM 128              // query rows per CTA
#define BN 128              // prototype rows per chunk (16 concepts)
#define NCHUNK (NP / BN)    // 16
#define NTHREADS 512        // 16 warps: warp_m = w>>2 (4, 32 rows), warp_n = w&3 (4, 32 cols)
#define NCTAS (NQ / BM)     // 256

// padded fp16 tile row stride: 128 halves = 256B + 16B pad (conflict-free ldmatrix)
#define TSTRIDE 272

#define OFF_A   0
#define OFF_B0  (BM * TSTRIDE)            // 34816
#define OFF_B1  (OFF_B0 + BN * TSTRIDE)   // 69632
#define OFF_RED (OFF_B1 + BN * TSTRIDE)   // 104448
#define SMEM_BYTES (OFF_RED + 2 * BM * 4) // 105472

__device__ float g_loss_sum;   // zero-init at load; reset by last CTA each call
__device__ int   g_pos_cnt;
__device__ unsigned int g_done;

// fp16 PERMUTED prototypes, written by cvt kernel each call.
// Within each 128-row chunk, proto (c_local, m) is stored at row
//   (c_local>>2)*32 + (m>>1)*8 + (c_local&3)*2 + (m&1)
// so that after MMA, thread t=lane&3 of each quad owns the full 8-proto group
// of concept warp_n*4 + t in its accumulator registers (no shuffles needed).
__device__ __half P16[NP * D_SZ];

__device__ __forceinline__ uint32_t smem_u32(const void* p) {
    uint32_t a;
    asm("{ .reg .u64 t; cvta.to.shared.u64 t, %1; cvt.u32.u64 %0, t; }" : "=r"(a) : "l"(p));
    return a;
}

__device__ __forceinline__ void ldsm_x4(uint32_t& r0, uint32_t& r1, uint32_t& r2, uint32_t& r3,
                                        uint32_t addr) {
    asm volatile("ldmatrix.sync.aligned.m8n8.x4.shared.b16 {%0,%1,%2,%3}, [%4];"
                 : "=r"(r0), "=r"(r1), "=r"(r2), "=r"(r3) : "r"(addr));
}

// fp16-accumulate HMMA: C/D = 2 b32 regs (4 halves).
// reg0 = (col 2t, col 2t+1) at row rlow;  reg1 = same cols at row rlow+8.
__device__ __forceinline__ void mma_f16acc(uint32_t* c, uint32_t a0, uint32_t a1, uint32_t a2,
                                           uint32_t a3, uint32_t b0, uint32_t b1) {
    asm volatile(
        "mma.sync.aligned.m16n8k16.row.col.f16.f16.f16.f16 "
        "{%0,%1}, {%2,%3,%4,%5}, {%6,%7}, {%0,%1};"
        : "+r"(c[0]), "+r"(c[1])
        : "r"(a0), "r"(a1), "r"(a2), "r"(a3), "r"(b0), "r"(b1));
}

__device__ __forceinline__ void cp_async16(uint32_t saddr, const void* gptr) {
    asm volatile("cp.async.cg.shared.global [%0], [%1], 16;" :: "r"(saddr), "l"(gptr));
}
#define CP_COMMIT() asm volatile("cp.async.commit_group;" ::: "memory")
#define CP_WAIT0()  asm volatile("cp.async.wait_group 0;" ::: "memory")

__device__ __forceinline__ uint32_t pack2h(float a, float b) {
    __half2 t = __floats2half2_rn(a, b);
    return *reinterpret_cast<uint32_t*>(&t);
}

// cp.async a 128-row x 128-col fp16 tile (row-major src) into padded smem layout
__device__ __forceinline__ void issue_tile(uint32_t dst_sb, const __half* __restrict__ src,
                                           int tid) {
    #pragma unroll
    for (int i = 0; i < 4; i++) {
        int linear = tid + i * NTHREADS;   // 16B line index (2048 total)
        int row  = linear >> 4;
        int line = linear & 15;
        cp_async16(dst_sb + (uint32_t)row * TSTRIDE + (uint32_t)line * 16,
                   src + (size_t)row * D_SZ + line * 8);
    }
    CP_COMMIT();
}

// ---- P fp32 -> fp16 with concept-ownership permutation ----
__global__ void mpc_cvt_kernel(const float* __restrict__ P) {
    int i = blockIdx.x * blockDim.x + threadIdx.x;   // float4 index
    if (i < NP * D_SZ / 4) {
        int row  = i >> 5;           // global proto row
        int col4 = i & 31;
        int chunk = row >> 7;
        int p     = row & 127;
        int c_loc = p >> 3, m = p & 7;
        int r2 = ((c_loc >> 2) << 5) + ((m >> 1) << 3) + ((c_loc & 3) << 1) + (m & 1);
        float4 v = __ldg(reinterpret_cast<const float4*>(P) + i);
        *reinterpret_cast<uint2*>(&P16[((size_t)((chunk << 7) + r2)) * D_SZ + col4 * 4]) =
            make_uint2(pack2h(v.x, v.y), pack2h(v.z, v.w));
    }
}

__global__ __launch_bounds__(NTHREADS, 2)
void mpc_main_kernel(const float* __restrict__ V,
                     const int*   __restrict__ labels,
                     float* __restrict__ out)
{
    extern __shared__ char smem[];
    const uint32_t sb = smem_u32(smem);
    const int tid  = threadIdx.x;
    const int warp = tid >> 5;
    const int lane = tid & 31;
    const int warp_m = warp >> 2;   // 0..3 -> rows 32*warp_m
    const int warp_n = warp & 3;    // 0..3 -> cols 32*warp_n
    const int rowBase = blockIdx.x * BM;
    const int kbase   = rowBase & (K_SZ - 1);   // 0 or 128

    float* denom_s = reinterpret_cast<float*>(smem + OFF_RED);
    float* sims_s  = denom_s + BM;
    if (tid < BM) { denom_s[tid] = 0.0f; sims_s[tid] = 0.0f; }

    // ---- B chunk 0 (fp16, permuted) via cp.async; A converted inline ----
    issue_tile(sb + OFF_B0, P16, tid);
    {
        const float4* gv = reinterpret_cast<const float4*>(V + (size_t)rowBase * D_SZ);
        #pragma unroll
        for (int i = 0; i < 8; i++) {
            int linear = tid + i * NTHREADS;   // float4 index (4096 total)
            int row  = linear >> 5;
            int col4 = linear & 31;
            float4 v = __ldg(gv + linear);
            *reinterpret_cast<uint2*>(smem + OFF_A + (uint32_t)row * TSTRIDE
                                      + (uint32_t)col4 * 8) =
                make_uint2(pack2h(v.x, v.y), pack2h(v.z, v.w));
        }
    }
    CP_WAIT0();
    __syncthreads();

    // lane-invariant ldmatrix address components
    const uint32_t aLane = (uint32_t)(warp_m * 32 + (lane & 15)) * TSTRIDE
                         + (uint32_t)(lane >> 4) * 16;
    const uint32_t bLane = (uint32_t)(warp_n * 32 + ((lane >> 4) << 3) + (lane & 7)) * TSTRIDE
                         + (uint32_t)((lane >> 3) & 1) * 16;
    const uint32_t aB0 = sb + OFF_A + aLane;
    const uint32_t aB1 = aB0 + 16u * TSTRIDE;

    // this thread's concept-within-chunk and rows
    const int ct    = warp_n * 4 + (lane & 3);
    const int rlow  = warp_m * 32 + (lane >> 2);   // + mf*16 + hr*8

    float denomAcc[4], simPos[4];   // [2*mf + hr]
    #pragma unroll
    for (int i = 0; i < 4; i++) { denomAcc[i] = 0.0f; simPos[i] = 0.0f; }

    #pragma unroll 1
    for (int chunk = 0; chunk < NCHUNK; ++chunk) {
        // prefetch next chunk's B into the other buffer (safe: last read pre-barrier)
        if (chunk + 1 < NCHUNK)
            issue_tile(sb + (((chunk + 1) & 1) ? OFF_B1 : OFF_B0),
                       P16 + (size_t)((chunk + 1) * BN) * D_SZ, tid);

        const uint32_t bB0 = sb + ((chunk & 1) ? OFF_B1 : OFF_B0) + bLane;
        const uint32_t bB1 = bB0 + 16u * TSTRIDE;

        // fp16x2 accumulators: acc[mf][nf][hr]; hr=0 row low, hr=1 row high
        uint32_t acc[2][4][2];
        #pragma unroll
        for (int mf = 0; mf < 2; mf++)
            #pragma unroll
            for (int nf = 0; nf < 4; nf++) {
                acc[mf][nf][0] = 0u;
                acc[mf][nf][1] = 0u;
            }

        // single-pass fp16, fp16 accumulate: per k-step 4 LDSM feed 8 MMAs
        #pragma unroll
        for (int ks = 0; ks < 8; ++ks) {
            const uint32_t ko = (uint32_t)ks * 32;
            uint32_t a0[4], a1[4];
            ldsm_x4(a0[0], a0[1], a0[2], a0[3], aB0 + ko);
            ldsm_x4(a1[0], a1[1], a1[2], a1[3], aB1 + ko);
            uint32_t b0, b1, b2, b3, b4, b5, b6, b7;
            ldsm_x4(b0, b1, b2, b3, bB0 + ko);   // rows 0-15 of slice: nf0, nf1
            ldsm_x4(b4, b5, b6, b7, bB1 + ko);   // rows 16-31: nf2, nf3

            mma_f16acc(acc[0][0], a0[0], a0[1], a0[2], a0[3], b0, b1);
            mma_f16acc(acc[0][1], a0[0], a0[1], a0[2], a0[3], b2, b3);
            mma_f16acc(acc[0][2], a0[0], a0[1], a0[2], a0[3], b4, b5);
            mma_f16acc(acc[0][3], a0[0], a0[1], a0[2], a0[3], b6, b7);
            mma_f16acc(acc[1][0], a1[0], a1[1], a1[2], a1[3], b0, b1);
            mma_f16acc(acc[1][1], a1[0], a1[1], a1[2], a1[3], b2, b3);
            mma_f16acc(acc[1][2], a1[0], a1[1], a1[2], a1[3], b4, b5);
            mma_f16acc(acc[1][3], a1[0], a1[1], a1[2], a1[3], b6, b7);
        }

        if (chunk + 1 < NCHUNK) CP_WAIT0();
        __syncthreads();

        // ---- register-local epilogue: thread owns concept ct's full 8-proto
        // group for rows rlow + mf*16 + hr*8 (permuted B). No shuffles. ----
        const int cg = chunk * 16 + ct;   // global concept this thread owns
        #pragma unroll
        for (int mf = 0; mf < 2; ++mf) {
            #pragma unroll
            for (int hr = 0; hr < 2; ++hr) {
                // proto pair (2nf, 2nf+1) = halves of acc[mf][nf][hr]
                float Z = 0.0f, W = 0.0f;
                #pragma unroll
                for (int nf = 0; nf < 4; ++nf) {
                    float2 f = __half22float2(
                        *reinterpret_cast<const __half2*>(&acc[mf][nf][hr]));
                    float ea = __expf(GAMMA_F * f.x);
                    float ec = __expf(GAMMA_F * f.y);
                    Z += ea + ec;
                    W = fmaf(ea, f.x, W);
                    W = fmaf(ec, f.y, W);
                }
                float sim = __fdividef(W, Z);
                denomAcc[2 * mf + hr] += __expf(LAMBDA_F * sim);
                int row = rlow + mf * 16 + hr * 8;
                if (cg == kbase + row) simPos[2 * mf + hr] = sim;
            }
        }
    }

    // ---- quad reduce (4 concepts -> per-row partials), then smem atomics ----
    #pragma unroll
    for (int o = 1; o <= 2; o <<= 1) {
        #pragma unroll
        for (int i = 0; i < 4; i++) {
            denomAcc[i] += __shfl_xor_sync(0xffffffffu, denomAcc[i], o);
            simPos[i]   += __shfl_xor_sync(0xffffffffu, simPos[i], o);
        }
    }
    __syncthreads();
    if ((lane & 3) == 0) {
        #pragma unroll
        for (int mf = 0; mf < 2; ++mf) {
            int r = rlow + mf * 16;
            atomicAdd(&denom_s[r],     denomAcc[2 * mf]);
            atomicAdd(&denom_s[r + 8], denomAcc[2 * mf + 1]);
            atomicAdd(&sims_s[r],      simPos[2 * mf]);
            atomicAdd(&sims_s[r + 8],  simPos[2 * mf + 1]);
        }
    }
    __syncthreads();

    float lsum = 0.0f;
    int   lcnt = 0;
    if (tid < BM) {
        float d = denom_s[tid];
        float p = sims_s[tid];
        float loss = __logf(d + EPS_F) - LAMBDA_F * (p + MARGIN_F);
        if (labels[rowBase + tid] == 1) { lsum = loss; lcnt = 1; }
    }
    #pragma unroll
    for (int o = 16; o > 0; o >>= 1) {
        lsum += __shfl_xor_sync(0xffffffffu, lsum, o);
        lcnt += __shfl_xor_sync(0xffffffffu, lcnt, o);
    }
    __shared__ float ws[16];
    __shared__ int   wc[16];
    if (lane == 0) { ws[warp] = lsum; wc[warp] = lcnt; }
    __syncthreads();

    // ---- single-launch finalize: last CTA writes out, resets globals ----
    if (tid == 0) {
        float s = 0.0f; int n = 0;
        #pragma unroll
        for (int i = 0; i < 16; i++) { s += ws[i]; n += wc[i]; }
        atomicAdd(&g_loss_sum, s);
        atomicAdd(&g_pos_cnt, n);
        __threadfence();
        unsigned int old = atomicAdd(&g_done, 1u);
        if (old == NCTAS - 1) {
            float ts = g_loss_sum;
            int   tn = g_pos_cnt;
            out[0] = (tn > 0) ? (ts / (float)tn) : ts;
            g_loss_sum = 0.0f;
            g_pos_cnt  = 0;
            __threadfence();
            g_done = 0u;
        }
    }
}

extern "C" void kernel_launch(void* const* d_in, const int* in_sizes, int n_in,
                              void* d_out, int out_size)
{
    const float* V = nullptr;
    const int*   L = nullptr;
    const float* P = nullptr;
    for (int i = 0; i < n_in; i++) {
        if      (in_sizes[i] == NQ * D_SZ) V = (const float*)d_in[i];
        else if (in_sizes[i] == NQ)        L = (const int*)d_in[i];
        else if (in_sizes[i] == NP * D_SZ) P = (const float*)d_in[i];
    }

    cudaFuncSetAttribute(mpc_main_kernel,
                         cudaFuncAttributeMaxDynamicSharedMemorySize, SMEM_BYTES);

    const int np4 = NP * D_SZ / 4;   // 65536 float4
    mpc_cvt_kernel<<<(np4 + 255) / 256, 256>>>(P);
    mpc_main_kernel<<<NCTAS, NTHREADS, SMEM_BYTES>>>(V, L, (float*)d_out);
}

// round 11
// speedup vs baseline: 1.4421x; 1.0944x over previous
#include <cuda_runtime.h>
#include <cuda_fp16.h>
#include <math.h>
#include <stdint.h>

// ---------------- problem constants ----------------
#define B_SZ   128
#define K_SZ   256
#define M_SZ   8
#define D_SZ   128
#define NQ     (B_SZ * K_SZ)   // 32768 query rows
#define NP     (K_SZ * M_SZ)   // 2048 prototype rows

#define GAMMA_F  20.0f
#define LAMBDA_F 20.0f
#define MARGIN_F 0.05f
#define EPS_F    1e-8f

// ---------------- tile config ----------------
#define BM 128              // query rows per CTA
#define BN 128              // prototype rows per chunk (16 concepts)
#define NCHUNK (NP / BN)    // 16
#define NTHREADS 512        // 16 warps: warp_m = w>>2 (4, 32 rows), warp_n = w&3 (4, 32 cols)
#define NCTAS (NQ / BM)     // 256

// padded fp16 A-tile row stride (conflict-free ldmatrix)
#define TSTRIDE 272

#define OFF_A   0
#define OFF_RED (BM * TSTRIDE)            // 34816
#define SMEM_BYTES (OFF_RED + 2 * BM * 4) // 35840

__device__ float g_loss_sum;   // zero-init at load; reset by last CTA each call
__device__ int   g_pos_cnt;
__device__ unsigned int g_done;

// Fragment-major fp16 prototypes (written by cvt kernel each call).
// For each (chunk, ks, warp_n): a 1024B block = 2 sub-blocks of 512B.
//   sub0: lane l's 16 bytes = regs b0..b3;  sub1: b4..b7.
// Register image matches what ldmatrix.x4 produced from the permuted smem
// tile in the previous kernel version: reg r of lane l = permuted-row
//   wn*32 + 16*(r>>2) + 8*((r>>1)&1) + (l>>2),  k = ks*16 + 8*(r&1) + 2*(l&3).
// Concept permutation (within a 128-row chunk): proto (c_loc, m) at row
//   (c_loc>>2)*32 + (m>>1)*8 + (c_loc&3)*2 + (m&1)
// so thread t=lane&3 of each quad owns concept warp_n*4+t's full 8-proto group.
// +2048 halves pad: last-iteration prefetch over-read lands in-bounds.
__device__ __half P16F[NP * D_SZ + 2048];

__device__ __forceinline__ uint32_t smem_u32(const void* p) {
    uint32_t a;
    asm("{ .reg .u64 t; cvta.to.shared.u64 t, %1; cvt.u32.u64 %0, t; }" : "=r"(a) : "l"(p));
    return a;
}

__device__ __forceinline__ void ldsm_x4(uint32_t& r0, uint32_t& r1, uint32_t& r2, uint32_t& r3,
                                        uint32_t addr) {
    asm volatile("ldmatrix.sync.aligned.m8n8.x4.shared.b16 {%0,%1,%2,%3}, [%4];"
                 : "=r"(r0), "=r"(r1), "=r"(r2), "=r"(r3) : "r"(addr));
}

// fp16-accumulate HMMA: C/D = 2 b32 regs (4 halves).
__device__ __forceinline__ void mma_f16acc(uint32_t* c, uint32_t a0, uint32_t a1, uint32_t a2,
                                           uint32_t a3, uint32_t b0, uint32_t b1) {
    asm volatile(
        "mma.sync.aligned.m16n8k16.row.col.f16.f16.f16.f16 "
        "{%0,%1}, {%2,%3,%4,%5}, {%6,%7}, {%0,%1};"
        : "+r"(c[0]), "+r"(c[1])
        : "r"(a0), "r"(a1), "r"(a2), "r"(a3), "r"(b0), "r"(b1));
}

__device__ __forceinline__ uint32_t pack2h(float a, float b) {
    __half2 t = __floats2half2_rn(a, b);
    return *reinterpret_cast<uint32_t*>(&t);
}

// ---- P fp32 -> fragment-major fp16 ----
// one thread per output uint32 (2 halves); 131072 total
__global__ void mpc_cvt_kernel(const float* __restrict__ P) {
    int i = blockIdx.x * blockDim.x + threadIdx.x;
    if (i < NP * D_SZ / 2) {
        int u   = i & 127;        // uint32 within 1024B... per (chunk,ks,wn,sub): 128 u32
        int l   = u >> 2;         // lane
        int rr  = u & 3;          // reg within sub-block
        int blk = i >> 7;
        int sub = blk & 1;
        int wn  = (blk >> 1) & 3;
        int ks  = (blk >> 3) & 7;
        int ch  = blk >> 6;
        int S = wn * 32 + sub * 16 + (rr >> 1) * 8 + (l >> 2);   // permuted row in chunk
        // invert permutation: S = a*32 + b*8 + d*2 + e -> c_loc = a*4+d, m = b*2+e
        int a = S >> 5, b = (S >> 3) & 3, d = (S >> 1) & 3, e = S & 1;
        int c_loc = a * 4 + d, m = b * 2 + e;
        int k0 = ks * 16 + (rr & 1) * 8 + (l & 3) * 2;
        float2 v = *reinterpret_cast<const float2*>(
            P + ((size_t)(ch * 128 + c_loc * 8 + m)) * D_SZ + k0);
        reinterpret_cast<uint32_t*>(P16F)[i] = pack2h(v.x, v.y);
    }
}

__global__ __launch_bounds__(NTHREADS, 2)
void mpc_main_kernel(const float* __restrict__ V,
                     const int*   __restrict__ labels,
                     float* __restrict__ out)
{
    extern __shared__ char smem[];
    const uint32_t sb = smem_u32(smem);
    const int tid  = threadIdx.x;
    const int warp = tid >> 5;
    const int lane = tid & 31;
    const int warp_m = warp >> 2;   // 0..3 -> rows 32*warp_m
    const int warp_n = warp & 3;    // 0..3 -> cols 32*warp_n
    const int rowBase = blockIdx.x * BM;
    const int kbase   = rowBase & (K_SZ - 1);   // 0 or 128

    float* denom_s = reinterpret_cast<float*>(smem + OFF_RED);
    float* sims_s  = denom_s + BM;
    if (tid < BM) { denom_s[tid] = 0.0f; sims_s[tid] = 0.0f; }

    // ---- prologue: A tile fp16 into smem (read-only afterwards) ----
    {
        const float4* gv = reinterpret_cast<const float4*>(V + (size_t)rowBase * D_SZ);
        #pragma unroll
        for (int i = 0; i < 8; i++) {
            int linear = tid + i * NTHREADS;   // float4 index (4096 total)
            int row  = linear >> 5;
            int col4 = linear & 31;
            float4 v = __ldg(gv + linear);
            *reinterpret_cast<uint2*>(smem + OFF_A + (uint32_t)row * TSTRIDE
                                      + (uint32_t)col4 * 8) =
                make_uint2(pack2h(v.x, v.y), pack2h(v.z, v.w));
        }
    }
    __syncthreads();   // the ONLY barrier before the reduction

    // lane-invariant A ldmatrix address components
    const uint32_t aLane = (uint32_t)(warp_m * 32 + (lane & 15)) * TSTRIDE
                         + (uint32_t)(lane >> 4) * 16;
    const uint32_t aB0 = sb + OFF_A + aLane;
    const uint32_t aB1 = aB0 + 16u * TSTRIDE;

    // this thread's concept-within-chunk and rows
    const int ct    = warp_n * 4 + (lane & 3);
    const int rlow  = warp_m * 32 + (lane >> 2);   // + mf*16 + hr*8

    // B fragment pointer (halves): block stride 2048, wn sub-offset 512, lane 8
    const __half* bp = P16F + warp_n * 512 + lane * 8;

    float denomAcc[4], simPos[4];   // [2*mf + hr]
    #pragma unroll
    for (int i = 0; i < 4; i++) { denomAcc[i] = 0.0f; simPos[i] = 0.0f; }

    // prime first ks block
    uint4 c0 = __ldg(reinterpret_cast<const uint4*>(bp));
    uint4 c1 = __ldg(reinterpret_cast<const uint4*>(bp + 256));

    #pragma unroll 1
    for (int chunk = 0; chunk < NCHUNK; ++chunk) {
        // fp16x2 accumulators: acc[mf][nf][hr]
        uint32_t acc[2][4][2];
        #pragma unroll
        for (int mf = 0; mf < 2; mf++)
            #pragma unroll
            for (int nf = 0; nf < 4; nf++) {
                acc[mf][nf][0] = 0u;
                acc[mf][nf][1] = 0u;
            }

        #pragma unroll
        for (int ks = 0; ks < 8; ++ks) {
            // prefetch next ks-block (pad absorbs final over-read)
            const __half* np_ = bp + (size_t)(chunk * 8 + ks + 1) * 2048;
            uint4 n0 = __ldg(reinterpret_cast<const uint4*>(np_));
            uint4 n1 = __ldg(reinterpret_cast<const uint4*>(np_ + 256));

            const uint32_t ko = (uint32_t)ks * 32;
            uint32_t a0[4], a1[4];
            ldsm_x4(a0[0], a0[1], a0[2], a0[3], aB0 + ko);
            ldsm_x4(a1[0], a1[1], a1[2], a1[3], aB1 + ko);

            mma_f16acc(acc[0][0], a0[0], a0[1], a0[2], a0[3], c0.x, c0.y);
            mma_f16acc(acc[0][1], a0[0], a0[1], a0[2], a0[3], c0.z, c0.w);
            mma_f16acc(acc[0][2], a0[0], a0[1], a0[2], a0[3], c1.x, c1.y);
            mma_f16acc(acc[0][3], a0[0], a0[1], a0[2], a0[3], c1.z, c1.w);
            mma_f16acc(acc[1][0], a1[0], a1[1], a1[2], a1[3], c0.x, c0.y);
            mma_f16acc(acc[1][1], a1[0], a1[1], a1[2], a1[3], c0.z, c0.w);
            mma_f16acc(acc[1][2], a1[0], a1[1], a1[2], a1[3], c1.x, c1.y);
            mma_f16acc(acc[1][3], a1[0], a1[1], a1[2], a1[3], c1.z, c1.w);

            c0 = n0;
            c1 = n1;
        }

        // ---- register-local epilogue (no barriers anywhere in this loop) ----
        const int cg = chunk * 16 + ct;   // global concept this thread owns
        #pragma unroll
        for (int mf = 0; mf < 2; ++mf) {
            #pragma unroll
            for (int hr = 0; hr < 2; ++hr) {
                float Z = 0.0f, W = 0.0f;
                #pragma unroll
                for (int nf = 0; nf < 4; ++nf) {
                    float2 f = __half22float2(
                        *reinterpret_cast<const __half2*>(&acc[mf][nf][hr]));
                    float ea = __expf(GAMMA_F * f.x);
                    float ec = __expf(GAMMA_F * f.y);
                    Z += ea + ec;
                    W = fmaf(ea, f.x, W);
                    W = fmaf(ec, f.y, W);
                }
                float sim = __fdividef(W, Z);
                denomAcc[2 * mf + hr] += __expf(LAMBDA_F * sim);
                int row = rlow + mf * 16 + hr * 8;
                if (cg == kbase + row) simPos[2 * mf + hr] = sim;
            }
        }
    }

    // ---- quad reduce (4 concepts -> per-row partials), then smem atomics ----
    #pragma unroll
    for (int o = 1; o <= 2; o <<= 1) {
        #pragma unroll
        for (int i = 0; i < 4; i++) {
            denomAcc[i] += __shfl_xor_sync(0xffffffffu, denomAcc[i], o);
            simPos[i]   += __shfl_xor_sync(0xffffffffu, simPos[i], o);
        }
    }
    if ((lane & 3) == 0) {
        #pragma unroll
        for (int mf = 0; mf < 2; ++mf) {
            int r = rlow + mf * 16;
            atomicAdd(&denom_s[r],     denomAcc[2 * mf]);
            atomicAdd(&denom_s[r + 8], denomAcc[2 * mf + 1]);
            atomicAdd(&sims_s[r],      simPos[2 * mf]);
            atomicAdd(&sims_s[r + 8],  simPos[2 * mf + 1]);
        }
    }
    __syncthreads();

    float lsum = 0.0f;
    int   lcnt = 0;
    if (tid < BM) {
        float d = denom_s[tid];
        float p = sims_s[tid];
        float loss = __logf(d + EPS_F) - LAMBDA_F * (p + MARGIN_F);
        if (labels[rowBase + tid] == 1) { lsum = loss; lcnt = 1; }
    }
    #pragma unroll
    for (int o = 16; o > 0; o >>= 1) {
        lsum += __shfl_xor_sync(0xffffffffu, lsum, o);
        lcnt += __shfl_xor_sync(0xffffffffu, lcnt, o);
    }
    __shared__ float ws[16];
    __shared__ int   wc[16];
    if (lane == 0) { ws[warp] = lsum; wc[warp] = lcnt; }
    __syncthreads();

    // ---- single-launch finalize: last CTA writes out, resets globals ----
    if (tid == 0) {
        float s = 0.0f; int n = 0;
        #pragma unroll
        for (int i = 0; i < 16; i++) { s += ws[i]; n += wc[i]; }
        atomicAdd(&g_loss_sum, s);
        atomicAdd(&g_pos_cnt, n);
        __threadfence();
        unsigned int old = atomicAdd(&g_done, 1u);
        if (old == NCTAS - 1) {
            float ts = g_loss_sum;
            int   tn = g_pos_cnt;
            out[0] = (tn > 0) ? (ts / (float)tn) : ts;
            g_loss_sum = 0.0f;
            g_pos_cnt  = 0;
            __threadfence();
            g_done = 0u;
        }
    }
}

extern "C" void kernel_launch(void* const* d_in, const int* in_sizes, int n_in,
                              void* d_out, int out_size)
{
    const float* V = nullptr;
    const int*   L = nullptr;
    const float* P = nullptr;
    for (int i = 0; i < n_in; i++) {
        if      (in_sizes[i] == NQ * D_SZ) V = (const float*)d_in[i];
        else if (in_sizes[i] == NQ)        L = (const int*)d_in[i];
        else if (in_sizes[i] == NP * D_SZ) P = (const float*)d_in[i];
    }

    cudaFuncSetAttribute(mpc_main_kernel,
                         cudaFuncAttributeMaxDynamicSharedMemorySize, SMEM_BYTES);

    const int nout = NP * D_SZ / 2;   // 131072 uint32
    mpc_cvt_kernel<<<(nout + 255) / 256, 256>>>(P);
    mpc_main_kernel<<<NCTAS, NTHREADS, SMEM_BYTES>>>(V, L, (float*)d_out);
}